// round 1
// baseline (speedup 1.0000x reference)
#include <cuda_runtime.h>
#include <math.h>

#define BB 16
#define GG 4
#define CGc 64
#define HH 64
#define WW 64
#define HWs 4096
#define KK 9

// scratch (static __device__ arrays; no allocation)
__device__ float g_off[BB*GG*18*HWs];        // predicted offsets [b][g][c=2k+j][h][w]
__device__ float g_wt [GG*KK*CGc*CGc];       // def_w transposed: [g][k][ic][oc]
__device__ float g_owt[GG*CGc*KK*20];        // off_w transposed: [g][ic][tap][c pad 20]

// ---------------- prep: weight transposes ----------------
__global__ void prep_kernel(const float* __restrict__ off_w,
                            const float* __restrict__ def_w) {
    int idx = blockIdx.x * blockDim.x + threadIdx.x;
    const int n_wt = GG*KK*CGc*CGc;   // 147456
    if (idx < n_wt) {
        int oc = idx & 63;
        int ic = (idx >> 6) & 63;
        int gk = idx >> 12;           // g*9+k
        int k  = gk % KK;
        int g  = gk / KK;
        g_wt[idx] = def_w[((g*CGc + oc)*CGc + ic)*KK + k];
    }
    const int n_owt = GG*CGc*KK*20;   // 46080
    if (idx < n_owt) {
        int c  = idx % 20;
        int t  = (idx / 20) % KK;
        int ic = (idx / 180) % CGc;
        int g  = idx / (180*CGc);
        g_owt[idx] = (c < 18) ? off_w[((g*18 + c)*CGc + ic)*KK + t] : 0.0f;
    }
}

// ---------------- offset conv: 64 -> 18, 3x3 ----------------
// block = (b,g,h); 256 threads = 64 w * 4 ic-chunks
extern __shared__ float smem1[];
__global__ void __launch_bounds__(256) offset_kernel(const float* __restrict__ x,
                                                     const float* __restrict__ off_b) {
    float* sx = smem1;              // 3*64*64 = 12288 floats (x tile, rows h-1..h+1)
    float* sw = smem1 + 12288;      // 64*9*20 = 11520 floats (transposed weights)

    int bid = blockIdx.x;
    int h = bid & 63;
    int g = (bid >> 6) & 3;
    int b = bid >> 8;
    int tid = threadIdx.x;

    const float* owt = g_owt + g*CGc*KK*20;
    for (int i = tid; i < CGc*KK*20; i += 256) sw[i] = owt[i];

    const float* xb = x + (size_t)(b*GG + g) * CGc * HWs;
    for (int i = tid; i < 3*CGc*WW; i += 256) {
        int ky = i >> 12;
        int ic = (i >> 6) & 63;
        int w  = i & 63;
        int row = h - 1 + ky;
        sx[i] = (row >= 0 && row < HH) ? xb[ic*HWs + row*WW + w] : 0.0f;
    }
    __syncthreads();

    int w   = tid & 63;
    int sub = tid >> 6;   // ic chunk 0..3

    float4 a4[5];
#pragma unroll
    for (int q = 0; q < 5; q++) a4[q] = make_float4(0.f,0.f,0.f,0.f);

#pragma unroll
    for (int ky = 0; ky < 3; ky++) {
        const float* sxk = sx + ky*4096;
        for (int ic = sub*16; ic < sub*16 + 16; ic++) {
            const float* xr = sxk + ic*64;
            float xv0 = (w > 0)  ? xr[w-1] : 0.0f;   // kx=0 -> col w-1
            float xv1 = xr[w];                        // kx=1
            float xv2 = (w < 63) ? xr[w+1] : 0.0f;   // kx=2
            const float4* wp = (const float4*)(sw + (ic*KK + ky*3)*20);
#pragma unroll
            for (int kx = 0; kx < 3; kx++) {
                float xs = (kx == 0) ? xv0 : ((kx == 1) ? xv1 : xv2);
#pragma unroll
                for (int q = 0; q < 5; q++) {
                    float4 wv = wp[kx*5 + q];
                    a4[q].x += wv.x * xs;
                    a4[q].y += wv.y * xs;
                    a4[q].z += wv.z * xs;
                    a4[q].w += wv.w * xs;
                }
            }
        }
    }
    __syncthreads();

    // partial-sum reduction via smem (reuse sx region): red[sub][c][w]
    float* red = sx;
#pragma unroll
    for (int q = 0; q < 5; q++) {
        int c = q*4;
        if (c+0 < 18) red[(sub*18 + c+0)*64 + w] = a4[q].x;
        if (c+1 < 18) red[(sub*18 + c+1)*64 + w] = a4[q].y;
        if (c+2 < 18) red[(sub*18 + c+2)*64 + w] = a4[q].z;
        if (c+3 < 18) red[(sub*18 + c+3)*64 + w] = a4[q].w;
    }
    __syncthreads();

    for (int i = tid; i < 18*64; i += 256) {
        int c = i >> 6, ww = i & 63;
        float s = red[(0*18 + c)*64 + ww] + red[(1*18 + c)*64 + ww]
                + red[(2*18 + c)*64 + ww] + red[(3*18 + c)*64 + ww]
                + off_b[g*18 + c];
        g_off[((size_t)(b*GG + g)*18 + c)*HWs + h*64 + ww] = s;
    }
}

// ---------------- deformable conv main kernel ----------------
// block = (b,g,h); 128 threads; per-tap: gather S[ic][w], GEMM 64oc x 64w x 64ic
extern __shared__ float smem2[];
__global__ void __launch_bounds__(128) deform_kernel(const float* __restrict__ x,
                                                     const float* __restrict__ def_b,
                                                     float* __restrict__ out) {
    float*  S  = smem2;                         // 4096 floats
    float*  Wt = smem2 + 4096;                  // 4096 floats  [ic][oc]
    float4* cw = (float4*)(smem2 + 8192);       // 576 float4: masked bilinear weights
    int4*   co = (int4*)  (smem2 + 8192 + 2304);// 576 int4: clamped corner offsets

    int bid = blockIdx.x;
    int h = bid & 63;
    int g = (bid >> 6) & 3;
    int b = bid >> 8;
    int tid = threadIdx.x;

    const float* xb = x + (size_t)(b*GG + g) * CGc * HWs;

    // precompute per-(tap,w) corner offsets + masked weights
    const float* offp = g_off + (size_t)(b*GG + g)*18*HWs + h*64;
    for (int i = tid; i < KK*64; i += 128) {
        int k = i >> 6, ww = i & 63;
        float dy = offp[(2*k    )*HWs + ww];
        float dx = offp[(2*k + 1)*HWs + ww];
        float py = dy + (float)(k/3 - 1) + (float)h;
        float px = dx + (float)(k%3 - 1) + (float)ww;
        float fy = floorf(py), fx = floorf(px);
        float wy = py - fy,    wx = px - fx;
        int y0 = (int)fy, x0 = (int)fx;
        int y1 = y0 + 1,  x1 = x0 + 1;
        float vy0 = (y0 >= 0 && y0 < HH) ? 1.f : 0.f;
        float vy1 = (y1 >= 0 && y1 < HH) ? 1.f : 0.f;
        float vx0 = (x0 >= 0 && x0 < WW) ? 1.f : 0.f;
        float vx1 = (x1 >= 0 && x1 < WW) ? 1.f : 0.f;
        float w00 = (1.f-wy)*(1.f-wx) * vy0 * vx0;
        float w01 = (1.f-wy)*wx       * vy0 * vx1;
        float w10 = wy*(1.f-wx)       * vy1 * vx0;
        float w11 = wy*wx             * vy1 * vx1;
        int y0c = min(max(y0,0),HH-1), y1c = min(max(y1,0),HH-1);
        int x0c = min(max(x0,0),WW-1), x1c = min(max(x1,0),WW-1);
        cw[i] = make_float4(w00, w01, w10, w11);
        co[i] = make_int4(y0c*WW + x0c, y0c*WW + x1c, y1c*WW + x0c, y1c*WW + x1c);
    }
    __syncthreads();

    float acc[8][4];
#pragma unroll
    for (int r = 0; r < 8; r++)
#pragma unroll
        for (int c = 0; c < 4; c++) acc[r][c] = 0.0f;

    int wq  = tid & 15;
    int ocq = tid >> 4;
    int w0  = wq * 4;
    int oc0 = ocq * 8;

    const float* wtg = g_wt + (size_t)g * KK * CGc * CGc;

    for (int k = 0; k < KK; k++) {
        // fill Wt[ic][oc] (coalesced float4 copy)
        {
            const float4* src = (const float4*)(wtg + k*CGc*CGc);
            float4* dst = (float4*)Wt;
            for (int i = tid; i < CGc*CGc/4; i += 128) dst[i] = src[i];
        }
        // fill S[ic][w]: 4-corner bilinear gather
        for (int i = tid; i < CGc*64; i += 128) {
            int ic = i >> 6, ww = i & 63;
            float4 wv = cw[k*64 + ww];
            int4   ov = co[k*64 + ww];
            const float* p = xb + ic*HWs;
            S[i] = wv.x * __ldg(p + ov.x) + wv.y * __ldg(p + ov.y)
                 + wv.z * __ldg(p + ov.z) + wv.w * __ldg(p + ov.w);
        }
        __syncthreads();

#pragma unroll 4
        for (int ic = 0; ic < CGc; ic++) {
            float4 sv = *(const float4*)(S  + ic*64 + w0);
            float4 a0 = *(const float4*)(Wt + ic*64 + oc0);
            float4 a1 = *(const float4*)(Wt + ic*64 + oc0 + 4);
#define FMA_ROW(r, wv) \
            acc[r][0] += (wv) * sv.x; acc[r][1] += (wv) * sv.y; \
            acc[r][2] += (wv) * sv.z; acc[r][3] += (wv) * sv.w;
            FMA_ROW(0, a0.x) FMA_ROW(1, a0.y) FMA_ROW(2, a0.z) FMA_ROW(3, a0.w)
            FMA_ROW(4, a1.x) FMA_ROW(5, a1.y) FMA_ROW(6, a1.z) FMA_ROW(7, a1.w)
#undef FMA_ROW
        }
        __syncthreads();
    }

    float* ob = out + (size_t)(b*GG + g)*CGc*HWs + h*64;
#pragma unroll
    for (int r = 0; r < 8; r++) {
        float bias = def_b[g*CGc + oc0 + r];
        float4 v = make_float4(acc[r][0] + bias, acc[r][1] + bias,
                               acc[r][2] + bias, acc[r][3] + bias);
        *(float4*)(ob + (oc0 + r)*HWs + w0) = v;
    }
}

// ---------------- launch ----------------
extern "C" void kernel_launch(void* const* d_in, const int* in_sizes, int n_in,
                              void* d_out, int out_size) {
    const float* x     = (const float*)d_in[0];
    const float* off_w = (const float*)d_in[1];
    const float* off_b = (const float*)d_in[2];
    const float* def_w = (const float*)d_in[3];
    const float* def_b = (const float*)d_in[4];
    float* out = (float*)d_out;

    // dynamic smem opt-in (idempotent; legal during graph capture)
    cudaFuncSetAttribute(offset_kernel, cudaFuncAttributeMaxDynamicSharedMemorySize,
                         (12288 + 11520) * (int)sizeof(float));   // 95232 B
    cudaFuncSetAttribute(deform_kernel, cudaFuncAttributeMaxDynamicSharedMemorySize,
                         12800 * (int)sizeof(float));             // 51200 B

    prep_kernel<<<(GG*KK*CGc*CGc + 255) / 256, 256>>>(off_w, def_w);
    offset_kernel<<<BB*GG*HH, 256, (12288 + 11520) * sizeof(float)>>>(x, off_b);
    deform_kernel<<<BB*GG*HH, 128, 12800 * sizeof(float)>>>(x, def_b, out);
}